// round 2
// baseline (speedup 1.0000x reference)
#include <cuda_runtime.h>
#include <cuda_fp16.h>
#include <cstdint>

// ---------------------------------------------------------------------------
// RNNT joiner: out[b,t,u,v] = sum_d relu(src[b,t,d]+tgt[b,u,d]) * W[v,d] + b[v]
// GEMM M=65536 (B*T*U), N=1024 (V), K=1024 (D).
// compute_103 target rejects tcgen05 => portable tensor path:
//   mma.sync.m16n8k16.f32.f16.f16.f32 + ldmatrix + cp.async.
// CTA tile 128x128x32, 256 threads (8 warps = 4m x 2n, warp tile 32x64),
// double-buffered smem, A=relu(src+tgt) built on the fly in fp16.
// ---------------------------------------------------------------------------

#define B_ 4
#define T_ 256
#define U_ 64
#define D_ 1024
#define V_ 1024

#define TILE_M 128
#define TILE_N 128
#define TILE_K 32
#define KITERS (D_ / TILE_K) /* 32 */
#define NTHREADS 256

#define PITCH 80                      /* 32 halfs = 64B + 16B pad: conflict-free ldmatrix */
#define STAGE_BYTES (128 * PITCH)     /* 10240 */
#define SMEM_DYN (4 * STAGE_BYTES)    /* A[2] + B[2] = 40960 */

__device__ __forceinline__ uint32_t smem_u32(const void* p) {
    uint32_t a;
    asm("{ .reg .u64 t; cvta.to.shared.u64 t, %1; cvt.u32.u64 %0, t; }" : "=r"(a) : "l"(p));
    return a;
}

__device__ __forceinline__ void sts128(uint32_t addr, uint32_t x, uint32_t y,
                                       uint32_t z, uint32_t w) {
    asm volatile("st.shared.v4.b32 [%0], {%1,%2,%3,%4};"
                 :: "r"(addr), "r"(x), "r"(y), "r"(z), "r"(w) : "memory");
}

__device__ __forceinline__ void cp16(uint32_t saddr, const void* g) {
    asm volatile("cp.async.cg.shared.global [%0], [%1], 16;" :: "r"(saddr), "l"(g) : "memory");
}
#define CP_COMMIT() asm volatile("cp.async.commit_group;" ::: "memory")
#define CP_WAIT0()  asm volatile("cp.async.wait_group 0;" ::: "memory")

__device__ __forceinline__ void ldsm_x4(uint32_t (&r)[4], uint32_t addr) {
    asm volatile("ldmatrix.sync.aligned.m8n8.x4.shared.b16 {%0,%1,%2,%3}, [%4];"
                 : "=r"(r[0]), "=r"(r[1]), "=r"(r[2]), "=r"(r[3]) : "r"(addr));
}

__device__ __forceinline__ void mma16816(float (&d)[4], const uint32_t (&a)[4],
                                         uint32_t b0, uint32_t b1) {
    asm volatile(
        "mma.sync.aligned.m16n8k16.row.col.f32.f16.f16.f32 "
        "{%0,%1,%2,%3}, {%4,%5,%6,%7}, {%8,%9}, {%0,%1,%2,%3};"
        : "+f"(d[0]), "+f"(d[1]), "+f"(d[2]), "+f"(d[3])
        : "r"(a[0]), "r"(a[1]), "r"(a[2]), "r"(a[3]), "r"(b0), "r"(b1));
}

__device__ __forceinline__ uint32_t h2u(__half2 h) { return *reinterpret_cast<uint32_t*>(&h); }

// W pre-converted to fp16, row-major [V][D]  (2 MB static device buffer)
__device__ __align__(16) __half g_Wh[(size_t)V_ * D_];

__global__ void convert_W_kernel(const float* __restrict__ W) {
    int i = blockIdx.x * blockDim.x + threadIdx.x;  // over V*D/4
    float4 v = reinterpret_cast<const float4*>(W)[i];
    __half2* dst = reinterpret_cast<__half2*>(g_Wh);
    dst[2 * i + 0] = __floats2half2_rn(v.x, v.y);
    dst[2 * i + 1] = __floats2half2_rn(v.z, v.w);
}

__global__ void __launch_bounds__(NTHREADS, 2) joiner_gemm(
    const float* __restrict__ src, const float* __restrict__ tgt,
    const float* __restrict__ bias, float* __restrict__ out) {
    extern __shared__ __align__(128) char smem[];
    const uint32_t A0 = smem_u32(smem);
    const uint32_t Bb0 = A0 + 2 * STAGE_BYTES;

    const int tid = threadIdx.x;
    const int wid = tid >> 5, lane = tid & 31;
    const int mt = blockIdx.x;   // 0..511
    const int nt = blockIdx.y;   // 0..7
    const int b = mt >> 7;       // 128 m-tiles per batch
    const int t0 = (mt & 127) * 2;

    // ---- fill-role mapping: thread -> (row r, k-half hf of 16 halfs) ----
    const int r = tid >> 1;
    const int hf = tid & 1;
    const int t = t0 + (r >> 6);
    const int u = r & 63;
    const float* srow = src + ((size_t)(b * T_ + t)) * D_ + hf * 16;
    const float* trow = tgt + ((size_t)(b * U_ + u)) * D_ + hf * 16;
    const __half* wrow = g_Wh + ((size_t)(nt * TILE_N + r)) * D_ + hf * 16;
    const uint32_t fill_off = (uint32_t)r * PITCH + hf * 32;

    // ---- mma-role mapping ----
    const int wm = wid & 3;            // 0..3 -> m
    const int wn = wid >> 2;           // 0..1 -> n
    const int m0w = wm * 32;
    const int n0w = wn * 64;
    const uint32_t a_ld_off = (uint32_t)(m0w + (lane & 15)) * PITCH + (lane >> 4) * 16;
    const uint32_t b_row = (uint32_t)(n0w + (lane & 7) + ((lane & 16) >> 1));
    const uint32_t b_ld_off = b_row * PITCH + ((lane >> 3) & 1) * 16;

    float acc[2][8][4];
#pragma unroll
    for (int mi = 0; mi < 2; mi++)
#pragma unroll
        for (int ni = 0; ni < 8; ni++)
#pragma unroll
            for (int q = 0; q < 4; q++) acc[mi][ni][q] = 0.f;

    auto fillA = [&](int s, int kt) {
        const float4* sp = reinterpret_cast<const float4*>(srow + kt * TILE_K);
        const float4* tp = reinterpret_cast<const float4*>(trow + kt * TILE_K);
        float4 s0 = sp[0], s1 = sp[1], s2 = sp[2], s3 = sp[3];
        float4 g0 = tp[0], g1 = tp[1], g2 = tp[2], g3 = tp[3];
        __half2 h0 = __floats2half2_rn(fmaxf(s0.x + g0.x, 0.f), fmaxf(s0.y + g0.y, 0.f));
        __half2 h1 = __floats2half2_rn(fmaxf(s0.z + g0.z, 0.f), fmaxf(s0.w + g0.w, 0.f));
        __half2 h2 = __floats2half2_rn(fmaxf(s1.x + g1.x, 0.f), fmaxf(s1.y + g1.y, 0.f));
        __half2 h3 = __floats2half2_rn(fmaxf(s1.z + g1.z, 0.f), fmaxf(s1.w + g1.w, 0.f));
        __half2 h4 = __floats2half2_rn(fmaxf(s2.x + g2.x, 0.f), fmaxf(s2.y + g2.y, 0.f));
        __half2 h5 = __floats2half2_rn(fmaxf(s2.z + g2.z, 0.f), fmaxf(s2.w + g2.w, 0.f));
        __half2 h6 = __floats2half2_rn(fmaxf(s3.x + g3.x, 0.f), fmaxf(s3.y + g3.y, 0.f));
        __half2 h7 = __floats2half2_rn(fmaxf(s3.z + g3.z, 0.f), fmaxf(s3.w + g3.w, 0.f));
        uint32_t a = A0 + s * STAGE_BYTES + fill_off;
        sts128(a,      h2u(h0), h2u(h1), h2u(h2), h2u(h3));
        sts128(a + 16, h2u(h4), h2u(h5), h2u(h6), h2u(h7));
    };

    auto loadB = [&](int s, int kt) {
        uint32_t d = Bb0 + s * STAGE_BYTES + fill_off;
        const __half* g = wrow + kt * TILE_K;
        cp16(d, g);
        cp16(d + 16, g + 8);
    };

    fillA(0, 0);
    loadB(0, 0);
    CP_COMMIT();

#pragma unroll 1
    for (int kt = 0; kt < KITERS; kt++) {
        const int cur = kt & 1;
        CP_WAIT0();
        __syncthreads();
        if (kt + 1 < KITERS) {
            fillA(cur ^ 1, kt + 1);
            loadB(cur ^ 1, kt + 1);
            CP_COMMIT();
        }
        const uint32_t Ab = A0 + cur * STAGE_BYTES;
        const uint32_t Bt = Bb0 + cur * STAGE_BYTES;
#pragma unroll
        for (int k16 = 0; k16 < 2; k16++) {
            const uint32_t kb = k16 * 32;
            uint32_t bfr[4][4];
#pragma unroll
            for (int p = 0; p < 4; p++)
                ldsm_x4(bfr[p], Bt + (uint32_t)(p * 16) * PITCH + b_ld_off + kb);
#pragma unroll
            for (int mi = 0; mi < 2; mi++) {
                uint32_t af[4];
                ldsm_x4(af, Ab + a_ld_off + (uint32_t)(mi * 16) * PITCH + kb);
#pragma unroll
                for (int ni = 0; ni < 8; ni++)
                    mma16816(acc[mi][ni], af, bfr[ni >> 1][(ni & 1) * 2],
                             bfr[ni >> 1][(ni & 1) * 2 + 1]);
            }
        }
    }

    // ---- epilogue: add bias, write fp32 ----
    const int g = lane >> 2;       // row within 8
    const int tig = lane & 3;      // col pair
    const int gn0 = nt * TILE_N + n0w;
    float2 bb[8];
#pragma unroll
    for (int ni = 0; ni < 8; ni++)
        bb[ni] = *reinterpret_cast<const float2*>(bias + gn0 + ni * 8 + tig * 2);

    const size_t rowbase = (size_t)mt * TILE_M + m0w;
#pragma unroll
    for (int mi = 0; mi < 2; mi++) {
        size_t r0 = rowbase + mi * 16 + g;
        size_t r1 = r0 + 8;
#pragma unroll
        for (int ni = 0; ni < 8; ni++) {
            float* p0 = out + r0 * (size_t)V_ + gn0 + ni * 8 + tig * 2;
            float* p1 = out + r1 * (size_t)V_ + gn0 + ni * 8 + tig * 2;
            float2 v0 = make_float2(acc[mi][ni][0] + bb[ni].x, acc[mi][ni][1] + bb[ni].y);
            float2 v1 = make_float2(acc[mi][ni][2] + bb[ni].x, acc[mi][ni][3] + bb[ni].y);
            *reinterpret_cast<float2*>(p0) = v0;
            *reinterpret_cast<float2*>(p1) = v1;
        }
    }
}

// Tail: source_lengths and target_lengths appended as value-cast floats.
__global__ void tail_kernel(const int* __restrict__ sl, const int* __restrict__ tl,
                            float* __restrict__ o, int n) {
    int i = threadIdx.x;
    if (i < n) {
        int v = (i < B_) ? sl[i] : ((i < 2 * B_) ? tl[i - B_] : 0);
        o[i] = (float)v;
    }
}

extern "C" void kernel_launch(void* const* d_in, const int* in_sizes, int n_in,
                              void* d_out, int out_size) {
    const float* src  = (const float*)d_in[0];
    const int*   slen = (const int*)d_in[1];
    const float* tgt  = (const float*)d_in[2];
    const int*   tlen = (const int*)d_in[3];
    const float* W    = (const float*)d_in[4];
    const float* bias = (const float*)d_in[5];
    float* out = (float*)d_out;

    convert_W_kernel<<<(V_ * D_ / 4) / 256, 256>>>(W);

    cudaFuncSetAttribute(joiner_gemm, cudaFuncAttributeMaxDynamicSharedMemorySize, SMEM_DYN);
    dim3 grid((B_ * T_ * U_) / TILE_M, V_ / TILE_N);  // (512, 8)
    joiner_gemm<<<grid, NTHREADS, SMEM_DYN>>>(src, tgt, bias, out);

    long long main_elems = (long long)B_ * T_ * U_ * V_;
    if ((long long)out_size > main_elems) {
        int ntail = (int)((long long)out_size - main_elems);
        if (ntail > 32) ntail = 32;
        tail_kernel<<<1, 32>>>(slen, tlen, out + main_elems, ntail);
    }
}

// round 3
// speedup vs baseline: 1.2328x; 1.2328x over previous
#include <cuda_runtime.h>
#include <cuda_fp16.h>
#include <cstdint>

// ---------------------------------------------------------------------------
// RNNT joiner, two-pass:
//   pass 1: Ah[m][d] = fp16(relu(src[b,t,d] + tgt[b,u,d]))   (m = b*T*U flat)
//   pass 2: out = Ah @ Wh^T + bias  (GEMM M=65536, N=1024, K=1024, HMMA fp16)
// GEMM: 128x128x32 CTA tile, 256 thr (8 warps = 4m x 2n, warp 32x64),
// 4-stage cp.async pipeline for BOTH operands, nt-fast grid for A L2 reuse.
// ---------------------------------------------------------------------------

#define B_ 4
#define T_ 256
#define U_ 64
#define D_ 1024
#define V_ 1024
#define M_ (B_ * T_ * U_)

#define TILE_M 128
#define TILE_N 128
#define TILE_K 32
#define KITERS (D_ / TILE_K) /* 32 */
#define NTHREADS 256
#define NSTAGE 4

#define PITCH 80                      /* 64B row + 16B pad: conflict-free ldmatrix */
#define STAGE_BYTES (128 * PITCH)     /* 10240 */
#define SMEM_DYN (2 * NSTAGE * STAGE_BYTES) /* A[4] + B[4] = 81920 */

__device__ __forceinline__ uint32_t smem_u32(const void* p) {
    uint32_t a;
    asm("{ .reg .u64 t; cvta.to.shared.u64 t, %1; cvt.u32.u64 %0, t; }" : "=r"(a) : "l"(p));
    return a;
}

__device__ __forceinline__ void cp16(uint32_t saddr, const void* g) {
    asm volatile("cp.async.cg.shared.global [%0], [%1], 16;" :: "r"(saddr), "l"(g) : "memory");
}
#define CP_COMMIT() asm volatile("cp.async.commit_group;" ::: "memory")
#define CP_WAIT2()  asm volatile("cp.async.wait_group 2;" ::: "memory")

__device__ __forceinline__ void ldsm_x4(uint32_t (&r)[4], uint32_t addr) {
    asm volatile("ldmatrix.sync.aligned.m8n8.x4.shared.b16 {%0,%1,%2,%3}, [%4];"
                 : "=r"(r[0]), "=r"(r[1]), "=r"(r[2]), "=r"(r[3]) : "r"(addr));
}

__device__ __forceinline__ void mma16816(float (&d)[4], const uint32_t (&a)[4],
                                         uint32_t b0, uint32_t b1) {
    asm volatile(
        "mma.sync.aligned.m16n8k16.row.col.f32.f16.f16.f32 "
        "{%0,%1,%2,%3}, {%4,%5,%6,%7}, {%8,%9}, {%0,%1,%2,%3};"
        : "+f"(d[0]), "+f"(d[1]), "+f"(d[2]), "+f"(d[3])
        : "r"(a[0]), "r"(a[1]), "r"(a[2]), "r"(a[3]), "r"(b0), "r"(b1));
}

__device__ __forceinline__ uint32_t h2u(__half2 h) { return *reinterpret_cast<uint32_t*>(&h); }

// Static scratch: W in fp16 (2 MB) and the materialized A operand (128 MB fp16).
__device__ __align__(16) __half g_Wh[(size_t)V_ * D_];
__device__ __align__(16) __half g_Ah[(size_t)M_ * D_];

__global__ void convert_W_kernel(const float* __restrict__ W) {
    int i = blockIdx.x * blockDim.x + threadIdx.x;  // over V*D/4
    float4 v = reinterpret_cast<const float4*>(W)[i];
    __half2* dst = reinterpret_cast<__half2*>(g_Wh);
    dst[2 * i + 0] = __floats2half2_rn(v.x, v.y);
    dst[2 * i + 1] = __floats2half2_rn(v.z, v.w);
}

// pass 1: build Ah = fp16(relu(src+tgt)); 8 elements per thread
__global__ void __launch_bounds__(256) build_A(const float* __restrict__ src,
                                               const float* __restrict__ tgt) {
    size_t i = (size_t)blockIdx.x * blockDim.x + threadIdx.x;  // over M*D/8
    int dc = (int)(i & (D_ / 8 - 1)) * 8;
    size_t row = i >> 7;
    int u = (int)(row & (U_ - 1));
    int t = (int)((row >> 6) & (T_ - 1));
    int b = (int)(row >> 14);
    const float4* sp = reinterpret_cast<const float4*>(src + ((size_t)(b * T_ + t)) * D_ + dc);
    const float4* tp = reinterpret_cast<const float4*>(tgt + ((size_t)(b * U_ + u)) * D_ + dc);
    float4 s0 = sp[0], s1 = sp[1];
    float4 g0 = tp[0], g1 = tp[1];
    __half2 h0 = __floats2half2_rn(fmaxf(s0.x + g0.x, 0.f), fmaxf(s0.y + g0.y, 0.f));
    __half2 h1 = __floats2half2_rn(fmaxf(s0.z + g0.z, 0.f), fmaxf(s0.w + g0.w, 0.f));
    __half2 h2 = __floats2half2_rn(fmaxf(s1.x + g1.x, 0.f), fmaxf(s1.y + g1.y, 0.f));
    __half2 h3 = __floats2half2_rn(fmaxf(s1.z + g1.z, 0.f), fmaxf(s1.w + g1.w, 0.f));
    *reinterpret_cast<uint4*>(g_Ah + row * D_ + dc) =
        make_uint4(h2u(h0), h2u(h1), h2u(h2), h2u(h3));
}

__global__ void __launch_bounds__(NTHREADS, 2) joiner_gemm(
    const float* __restrict__ bias, float* __restrict__ out) {
    extern __shared__ __align__(128) char smem[];
    const uint32_t A0 = smem_u32(smem);
    const uint32_t Bb0 = A0 + NSTAGE * STAGE_BYTES;

    const int tid = threadIdx.x;
    const int wid = tid >> 5, lane = tid & 31;
    const int nt = blockIdx.x;   // 0..7   (nt-fast: 8 CTAs share one A tile in L2)
    const int mt = blockIdx.y;   // 0..511

    // ---- load-role mapping: thread -> (row r, 16-half chunk hf) ----
    const int r = tid >> 1;
    const int hf = tid & 1;
    const __half* arow = g_Ah + ((size_t)(mt * TILE_M + r)) * D_ + hf * 16;
    const __half* wrow = g_Wh + ((size_t)(nt * TILE_N + r)) * D_ + hf * 16;
    const uint32_t fill_off = (uint32_t)r * PITCH + hf * 32;

    // ---- mma-role mapping ----
    const int wm = wid & 3;            // 0..3 -> m
    const int wn = wid >> 2;           // 0..1 -> n
    const int m0w = wm * 32;
    const int n0w = wn * 64;
    const uint32_t a_ld_off = (uint32_t)(m0w + (lane & 15)) * PITCH + (lane >> 4) * 16;
    const uint32_t b_row = (uint32_t)(n0w + (lane & 7) + ((lane & 16) >> 1));
    const uint32_t b_ld_off = b_row * PITCH + ((lane >> 3) & 1) * 16;

    float acc[2][8][4];
#pragma unroll
    for (int mi = 0; mi < 2; mi++)
#pragma unroll
        for (int ni = 0; ni < 8; ni++)
#pragma unroll
            for (int q = 0; q < 4; q++) acc[mi][ni][q] = 0.f;

    auto loadStage = [&](int s, int kt) {
        const __half* ga = arow + kt * TILE_K;
        const __half* gb = wrow + kt * TILE_K;
        uint32_t da = A0 + s * STAGE_BYTES + fill_off;
        uint32_t db = Bb0 + s * STAGE_BYTES + fill_off;
        cp16(da, ga);
        cp16(da + 16, ga + 8);
        cp16(db, gb);
        cp16(db + 16, gb + 8);
    };

    // prologue: stages 0,1,2 in flight
#pragma unroll
    for (int s = 0; s < NSTAGE - 1; s++) {
        loadStage(s, s);
        CP_COMMIT();
    }

#pragma unroll 1
    for (int kt = 0; kt < KITERS; kt++) {
        const int cur = kt & (NSTAGE - 1);
        CP_WAIT2();          // stage `cur` complete (<=2 newer groups pending)
        __syncthreads();     // visibility + safe to overwrite stage cur-1
        if (kt + NSTAGE - 1 < KITERS)
            loadStage((kt + NSTAGE - 1) & (NSTAGE - 1), kt + NSTAGE - 1);
        CP_COMMIT();         // always commit (possibly-empty group keeps count uniform)

        const uint32_t Ab = A0 + cur * STAGE_BYTES;
        const uint32_t Bt = Bb0 + cur * STAGE_BYTES;
#pragma unroll
        for (int k16 = 0; k16 < 2; k16++) {
            const uint32_t kb = k16 * 32;
            uint32_t bfr[4][4];
#pragma unroll
            for (int p = 0; p < 4; p++)
                ldsm_x4(bfr[p], Bt + (uint32_t)(p * 16) * PITCH + b_ld_off + kb);
#pragma unroll
            for (int mi = 0; mi < 2; mi++) {
                uint32_t af[4];
                ldsm_x4(af, Ab + a_ld_off + (uint32_t)(mi * 16) * PITCH + kb);
#pragma unroll
                for (int ni = 0; ni < 8; ni++)
                    mma16816(acc[mi][ni], af, bfr[ni >> 1][(ni & 1) * 2],
                             bfr[ni >> 1][(ni & 1) * 2 + 1]);
            }
        }
    }

    // ---- epilogue: add bias, write fp32 ----
    const int g = lane >> 2;
    const int tig = lane & 3;
    const int gn0 = nt * TILE_N + n0w;
    float2 bb[8];
#pragma unroll
    for (int ni = 0; ni < 8; ni++)
        bb[ni] = *reinterpret_cast<const float2*>(bias + gn0 + ni * 8 + tig * 2);

    const size_t rowbase = (size_t)mt * TILE_M + m0w;
#pragma unroll
    for (int mi = 0; mi < 2; mi++) {
        size_t r0 = rowbase + mi * 16 + g;
        size_t r1 = r0 + 8;
#pragma unroll
        for (int ni = 0; ni < 8; ni++) {
            float* p0 = out + r0 * (size_t)V_ + gn0 + ni * 8 + tig * 2;
            float* p1 = out + r1 * (size_t)V_ + gn0 + ni * 8 + tig * 2;
            *reinterpret_cast<float2*>(p0) =
                make_float2(acc[mi][ni][0] + bb[ni].x, acc[mi][ni][1] + bb[ni].y);
            *reinterpret_cast<float2*>(p1) =
                make_float2(acc[mi][ni][2] + bb[ni].x, acc[mi][ni][3] + bb[ni].y);
        }
    }
}

// Tail: source_lengths and target_lengths appended as value-cast floats.
__global__ void tail_kernel(const int* __restrict__ sl, const int* __restrict__ tl,
                            float* __restrict__ o, int n) {
    int i = threadIdx.x;
    if (i < n) {
        int v = (i < B_) ? sl[i] : ((i < 2 * B_) ? tl[i - B_] : 0);
        o[i] = (float)v;
    }
}

extern "C" void kernel_launch(void* const* d_in, const int* in_sizes, int n_in,
                              void* d_out, int out_size) {
    const float* src  = (const float*)d_in[0];
    const int*   slen = (const int*)d_in[1];
    const float* tgt  = (const float*)d_in[2];
    const int*   tlen = (const int*)d_in[3];
    const float* W    = (const float*)d_in[4];
    const float* bias = (const float*)d_in[5];
    float* out = (float*)d_out;

    convert_W_kernel<<<(V_ * D_ / 4) / 256, 256>>>(W);
    build_A<<<((size_t)M_ * D_ / 8) / 256, 256>>>(src, tgt);

    cudaFuncSetAttribute(joiner_gemm, cudaFuncAttributeMaxDynamicSharedMemorySize, SMEM_DYN);
    dim3 grid(V_ / TILE_N, M_ / TILE_M);  // (8, 512) nt-fast
    joiner_gemm<<<grid, NTHREADS, SMEM_DYN>>>(bias, out);

    long long main_elems = (long long)M_ * V_;
    if ((long long)out_size > main_elems) {
        int ntail = (int)((long long)out_size - main_elems);
        if (ntail > 32) ntail = 32;
        tail_kernel<<<1, 32>>>(slen, tlen, out + main_elems, ntail);
    }
}